// round 1
// baseline (speedup 1.0000x reference)
#include <cuda_runtime.h>

#define N_NODES 20000
#define N_EDGES 640000
#define NHEAD 8

// CSR scratch (device globals — no allocation allowed)
__device__ int g_counts[N_NODES];
__device__ int g_offsets[N_NODES + 1];
__device__ int g_cursor[N_NODES];
__device__ int g_edge_idx[N_EDGES];

__global__ void k_zero() {
    int i = blockIdx.x * blockDim.x + threadIdx.x;
    if (i < N_NODES) g_counts[i] = 0;
}

__global__ void k_hist(const int* __restrict__ dst) {
    int e = blockIdx.x * blockDim.x + threadIdx.x;
    if (e < N_EDGES) atomicAdd(&g_counts[dst[e]], 1);
}

// Single-block exclusive scan over counts -> offsets, also init cursor.
__global__ void k_scan() {
    __shared__ int tmp[1024];
    __shared__ int carry_s;
    int t = threadIdx.x;
    if (t == 0) carry_s = 0;
    __syncthreads();
    for (int base = 0; base < N_NODES; base += 1024) {
        int v = (base + t < N_NODES) ? g_counts[base + t] : 0;
        tmp[t] = v;
        __syncthreads();
        #pragma unroll
        for (int off = 1; off < 1024; off <<= 1) {
            int add = (t >= off) ? tmp[t - off] : 0;
            __syncthreads();
            tmp[t] += add;
            __syncthreads();
        }
        int carry = carry_s;
        int excl = carry + tmp[t] - v;
        if (base + t < N_NODES) {
            g_offsets[base + t] = excl;
            g_cursor[base + t] = excl;
        }
        int total = tmp[1023];
        __syncthreads();
        if (t == 0) carry_s = carry + total;
        __syncthreads();
    }
    if (t == 0) g_offsets[N_NODES] = carry_s;
}

__global__ void k_place(const int* __restrict__ dst) {
    int e = blockIdx.x * blockDim.x + threadIdx.x;
    if (e < N_EDGES) {
        int pos = atomicAdd(&g_cursor[dst[e]], 1);
        g_edge_idx[pos] = e;
    }
}

// One block (4 warps) per node. Warp handles one edge at a time:
//  - lane l loads float4 of key_feat (512B coalesced); per-head (16-dim) dot
//    via 2x shfl_xor within lane-groups of 4 (head h = lane/4).
//  - prelogits written (contiguous 32B per edge).
//  - exp(p) accumulated into per-lane s (division deferred; max skipped:
//    logits have sigma ~0.35, exp cannot overflow).
//  - value: lane l accumulates flat elements l+32k, k=0..5 (6x coalesced
//    128B loads/warp/edge); head of element j is j/24, ex fetched via shfl.
// Cross-warp reduce through smem atomics, then normalize + write outputs.
__global__ __launch_bounds__(128) void k_main(
    const float* __restrict__ value,
    const float* __restrict__ key_feat,
    const float* __restrict__ q0,
    const float* __restrict__ q1,
    float* __restrict__ out0,
    float* __restrict__ out1,
    float* __restrict__ prelogits)
{
    int n = blockIdx.x;
    int t = threadIdx.x;
    int lane = t & 31;
    int warp = t >> 5;

    __shared__ float4 qs4[32];
    __shared__ float sacc[192];
    __shared__ float ssum[NHEAD];
    float* qs = (float*)qs4;

    // Build q[n] in flat (8,16) layout:
    // channel c (0..31): [q0[c], q1[c,0], q1[c,1], q1[c,2]] at qs[4c .. 4c+3]
    if (t < 32) qs[t * 4] = q0[n * 32 + t];
    if (t >= 32) {                      // t-32 in [0,96)
        int u = t - 32;
        qs[(u / 3) * 4 + 1 + (u % 3)] = q1[n * 96 + u];
    }
    sacc[t] = 0.f;
    if (t < 64) sacc[128 + t] = 0.f;
    if (t < NHEAD) ssum[t] = 0.f;
    __syncthreads();

    int off = g_offsets[n];
    int deg = g_offsets[n + 1] - off;

    // source lane (group leader 4*h) for each of this lane's 6 value elements
    int src_lane[6];
    #pragma unroll
    for (int k = 0; k < 6; k++) src_lane[k] = 4 * ((lane + 32 * k) / 24);

    float acc[6] = {0.f, 0.f, 0.f, 0.f, 0.f, 0.f};
    float s_reg = 0.f;
    const float scale = 0.08838834764831845f;  // 1/sqrt(128)

    float4 qv = qs4[lane];

    for (int idx = warp; idx < deg; idx += 4) {
        int e = g_edge_idx[off + idx];
        float4 kv = ((const float4*)key_feat)[e * 32 + lane];
        float p = kv.x * qv.x + kv.y * qv.y + kv.z * qv.z + kv.w * qv.w;
        p += __shfl_xor_sync(0xffffffffu, p, 1);
        p += __shfl_xor_sync(0xffffffffu, p, 2);
        p *= scale;
        if ((lane & 3) == 0) prelogits[e * 8 + (lane >> 2)] = p;
        float ex = __expf(p);
        if ((lane & 3) == 0) s_reg += ex;

        const float* vp = value + e * 192 + lane;
        #pragma unroll
        for (int k = 0; k < 6; k++) {
            float exk = __shfl_sync(0xffffffffu, ex, src_lane[k]);
            acc[k] += exk * vp[32 * k];
        }
    }

    #pragma unroll
    for (int k = 0; k < 6; k++) atomicAdd(&sacc[lane + 32 * k], acc[k]);
    if ((lane & 3) == 0) atomicAdd(&ssum[lane >> 2], s_reg);
    __syncthreads();

    // feat flat index j in (64,3): out0 takes (c<32, d=0) -> j=3c, head c/8
    //                              out1 takes (c>=32, all d) -> j=96+u, head 4+u/24
    if (t < 32) {
        float s = ssum[t >> 3];
        out0[n * 32 + t] = (s > 0.f) ? sacc[3 * t] / s : 0.f;
    } else {
        int u = t - 32;  // 0..95
        float s = ssum[4 + u / 24];
        out1[n * 96 + u] = (s > 0.f) ? sacc[96 + u] / s : 0.f;
    }
}

extern "C" void kernel_launch(void* const* d_in, const int* in_sizes, int n_in,
                              void* d_out, int out_size)
{
    const float* value    = (const float*)d_in[0];
    const float* key_feat = (const float*)d_in[1];
    const float* q0       = (const float*)d_in[2];
    const float* q1       = (const float*)d_in[3];
    const int*   dst      = (const int*)d_in[4];

    float* out       = (float*)d_out;
    float* out0      = out;                 // N*32*1
    float* out1      = out + 640000;        // N*32*3
    float* prelogits = out + 2560000;       // E*8

    k_zero<<<(N_NODES + 511) / 512, 512>>>();
    k_hist<<<(N_EDGES + 255) / 256, 256>>>(dst);
    k_scan<<<1, 1024>>>();
    k_place<<<(N_EDGES + 255) / 256, 256>>>(dst);
    k_main<<<N_NODES, 128>>>(value, key_feat, q0, q1, out0, out1, prelogits);
}

// round 4
// speedup vs baseline: 1.4921x; 1.4921x over previous
#include <cuda_runtime.h>

#define N_NODES 20000
#define N_EDGES 640000
#define NHEAD 8

// CSR scratch (device globals — no allocation allowed)
__device__ int g_counts[N_NODES];
__device__ int g_offsets[N_NODES + 1];
__device__ int g_cursor[N_NODES];
__device__ int g_edge_idx[N_EDGES];

__global__ void k_zero() {
    int i = blockIdx.x * blockDim.x + threadIdx.x;
    if (i < N_NODES) g_counts[i] = 0;
}

// 4 edges per thread via int4
__global__ void k_hist(const int* __restrict__ dst) {
    int i = blockIdx.x * blockDim.x + threadIdx.x;
    if (i < N_EDGES / 4) {
        int4 d = ((const int4*)dst)[i];
        atomicAdd(&g_counts[d.x], 1);
        atomicAdd(&g_counts[d.y], 1);
        atomicAdd(&g_counts[d.z], 1);
        atomicAdd(&g_counts[d.w], 1);
    }
}

// Single-block one-pass scan: thread t owns 20 contiguous counts.
// warp-shfl scan of the 1024 per-thread sums, 2 barriers total.
__global__ __launch_bounds__(1024) void k_scan() {
    const int PER = 20;                       // 1024*20 = 20480 >= 20000
    int t = threadIdx.x;
    int lane = t & 31, w = t >> 5;
    int base = t * PER;

    int c[PER];
    int sum = 0;
    #pragma unroll
    for (int j = 0; j < PER; j++) {
        int idx = base + j;
        c[j] = (idx < N_NODES) ? g_counts[idx] : 0;
        sum += c[j];
    }

    // inclusive warp scan of sum
    int inc = sum;
    #pragma unroll
    for (int o = 1; o < 32; o <<= 1) {
        int nv = __shfl_up_sync(0xffffffffu, inc, o);
        if (lane >= o) inc += nv;
    }
    __shared__ int wsum[32];
    if (lane == 31) wsum[w] = inc;
    __syncthreads();
    if (w == 0) {
        int v = wsum[lane];
        #pragma unroll
        for (int o = 1; o < 32; o <<= 1) {
            int nv = __shfl_up_sync(0xffffffffu, v, o);
            if (lane >= o) v += nv;
        }
        wsum[lane] = v;
    }
    __syncthreads();

    int excl = ((w > 0) ? wsum[w - 1] : 0) + inc - sum;
    int running = excl;
    #pragma unroll
    for (int j = 0; j < PER; j++) {
        int idx = base + j;
        if (idx < N_NODES) {
            g_offsets[idx] = running;
            g_cursor[idx] = running;
        }
        running += c[j];
    }
    if (t == 1023) g_offsets[N_NODES] = running;
}

__global__ void k_place(const int* __restrict__ dst) {
    int i = blockIdx.x * blockDim.x + threadIdx.x;
    if (i < N_EDGES / 4) {
        int4 d = ((const int4*)dst)[i];
        int e = i * 4;
        g_edge_idx[atomicAdd(&g_cursor[d.x], 1)] = e;
        g_edge_idx[atomicAdd(&g_cursor[d.y], 1)] = e + 1;
        g_edge_idx[atomicAdd(&g_cursor[d.z], 1)] = e + 2;
        g_edge_idx[atomicAdd(&g_cursor[d.w], 1)] = e + 3;
    }
}

// One block (4 warps) per node.
// Per edge per warp:
//   - lane l loads float4 of key_feat (512B coalesced); head h = l/4;
//     16-dim dot via 2x shfl_xor within lane-groups of 4.
//   - lane l owns flat value elements [6l, 6l+6): since 6*(l%4)+5 < 24,
//     the whole range is in head l/4 = the lane's own head, so the lane's
//     own ex weights them — NO broadcast shfls. 3x LDG.64, fully coalesced
//     (768B per warp per edge).
//   - softmax max skipped (logits sigma~0.35, exp can't overflow; w is
//     shift-invariant); division deferred to epilogue.
// 2x edge unroll for MLP; __ldcs streaming hints (zero reuse).
__global__ __launch_bounds__(128) void k_main(
    const float* __restrict__ value,
    const float* __restrict__ key_feat,
    const float* __restrict__ q0,
    const float* __restrict__ q1,
    float* __restrict__ out0,
    float* __restrict__ out1,
    float* __restrict__ prelogits)
{
    int n = blockIdx.x;
    int t = threadIdx.x;
    int lane = t & 31;
    int warp = t >> 5;

    __shared__ float4 qs4[32];
    __shared__ float sacc[192];
    __shared__ float ssum[NHEAD];
    float* qs = (float*)qs4;

    // q[n] flat (8,16): channel c: [q0[c], q1[c,0..2]] at qs[4c..4c+3]
    if (t < 32) qs[t * 4] = q0[n * 32 + t];
    if (t >= 32) {
        int u = t - 32;                 // [0,96)
        qs[(u / 3) * 4 + 1 + (u % 3)] = q1[n * 96 + u];
    }
    sacc[t] = 0.f;
    if (t < 64) sacc[128 + t] = 0.f;
    if (t < NHEAD) ssum[t] = 0.f;
    __syncthreads();

    int off = g_offsets[n];
    int deg = g_offsets[n + 1] - off;

    float acc[6] = {0.f, 0.f, 0.f, 0.f, 0.f, 0.f};
    float s_reg = 0.f;
    const float scale = 0.08838834764831845f;  // 1/sqrt(128)
    bool leader = (lane & 3) == 0;
    int h = lane >> 2;

    float4 qv = qs4[lane];

    int idx = warp;
    for (; idx + 4 < deg; idx += 8) {
        int e0 = g_edge_idx[off + idx];
        int e1 = g_edge_idx[off + idx + 4];
        const float4* kp0 = (const float4*)key_feat + e0 * 32 + lane;
        const float4* kp1 = (const float4*)key_feat + e1 * 32 + lane;
        const float2* vp0 = (const float2*)(value + e0 * 192) + 3 * lane;
        const float2* vp1 = (const float2*)(value + e1 * 192) + 3 * lane;

        float4 k0 = __ldcs(kp0);
        float4 k1 = __ldcs(kp1);
        float2 a0 = __ldcs(vp0), a1 = __ldcs(vp0 + 1), a2 = __ldcs(vp0 + 2);
        float2 b0 = __ldcs(vp1), b1 = __ldcs(vp1 + 1), b2 = __ldcs(vp1 + 2);

        float p0 = k0.x * qv.x + k0.y * qv.y + k0.z * qv.z + k0.w * qv.w;
        float p1 = k1.x * qv.x + k1.y * qv.y + k1.z * qv.z + k1.w * qv.w;
        p0 += __shfl_xor_sync(0xffffffffu, p0, 1);
        p1 += __shfl_xor_sync(0xffffffffu, p1, 1);
        p0 += __shfl_xor_sync(0xffffffffu, p0, 2);
        p1 += __shfl_xor_sync(0xffffffffu, p1, 2);
        p0 *= scale;
        p1 *= scale;
        if (leader) {
            prelogits[e0 * 8 + h] = p0;
            prelogits[e1 * 8 + h] = p1;
        }
        float ex0 = __expf(p0);
        float ex1 = __expf(p1);
        if (leader) s_reg += ex0 + ex1;

        acc[0] += ex0 * a0.x; acc[1] += ex0 * a0.y;
        acc[2] += ex0 * a1.x; acc[3] += ex0 * a1.y;
        acc[4] += ex0 * a2.x; acc[5] += ex0 * a2.y;
        acc[0] += ex1 * b0.x; acc[1] += ex1 * b0.y;
        acc[2] += ex1 * b1.x; acc[3] += ex1 * b1.y;
        acc[4] += ex1 * b2.x; acc[5] += ex1 * b2.y;
    }
    if (idx < deg) {
        int e0 = g_edge_idx[off + idx];
        const float4* kp0 = (const float4*)key_feat + e0 * 32 + lane;
        const float2* vp0 = (const float2*)(value + e0 * 192) + 3 * lane;
        float4 k0 = __ldcs(kp0);
        float2 a0 = __ldcs(vp0), a1 = __ldcs(vp0 + 1), a2 = __ldcs(vp0 + 2);
        float p0 = k0.x * qv.x + k0.y * qv.y + k0.z * qv.z + k0.w * qv.w;
        p0 += __shfl_xor_sync(0xffffffffu, p0, 1);
        p0 += __shfl_xor_sync(0xffffffffu, p0, 2);
        p0 *= scale;
        if (leader) prelogits[e0 * 8 + h] = p0;
        float ex0 = __expf(p0);
        if (leader) s_reg += ex0;
        acc[0] += ex0 * a0.x; acc[1] += ex0 * a0.y;
        acc[2] += ex0 * a1.x; acc[3] += ex0 * a1.y;
        acc[4] += ex0 * a2.x; acc[5] += ex0 * a2.y;
    }

    #pragma unroll
    for (int j = 0; j < 6; j++) atomicAdd(&sacc[6 * lane + j], acc[j]);
    if (leader) atomicAdd(&ssum[h], s_reg);
    __syncthreads();

    // feat flat j in (64,3): out0 = (c<32, d=0) -> j=3c, head c/8
    //                        out1 = (c>=32)     -> j=96+u, head 4+u/24
    if (t < 32) {
        float s = ssum[t >> 3];
        out0[n * 32 + t] = (s > 0.f) ? sacc[3 * t] / s : 0.f;
    } else {
        int u = t - 32;
        float s = ssum[4 + u / 24];
        out1[n * 96 + u] = (s > 0.f) ? sacc[96 + u] / s : 0.f;
    }
}

extern "C" void kernel_launch(void* const* d_in, const int* in_sizes, int n_in,
                              void* d_out, int out_size)
{
    const float* value    = (const float*)d_in[0];
    const float* key_feat = (const float*)d_in[1];
    const float* q0       = (const float*)d_in[2];
    const float* q1       = (const float*)d_in[3];
    const int*   dst      = (const int*)d_in[4];

    float* out       = (float*)d_out;
    float* out0      = out;                 // N*32*1
    float* out1      = out + 640000;        // N*32*3
    float* prelogits = out + 2560000;       // E*8

    k_zero<<<(N_NODES + 511) / 512, 512>>>();
    k_hist<<<(N_EDGES / 4 + 255) / 256, 256>>>(dst);
    k_scan<<<1, 1024>>>();
    k_place<<<(N_EDGES / 4 + 255) / 256, 256>>>(dst);
    k_main<<<N_NODES, 128>>>(value, key_feat, q0, q1, out0, out1, prelogits);
}

// round 5
// speedup vs baseline: 1.5029x; 1.0072x over previous
#include <cuda_runtime.h>

#define N_NODES 20000
#define N_EDGES 640000
#define NHEAD 8

// CSR scratch (device globals — no allocation allowed)
// g_counts is zero at module load; k_place re-zeroes it each execution so
// every run (correctness + each graph replay) starts from counts==0.
__device__ int g_counts[N_NODES];
__device__ int g_offsets[N_NODES + 1];
__device__ int g_cursor[N_NODES];
__device__ int g_edge_idx[N_EDGES];

// 8 edges per thread via 2x int4 — all 8 atomics independent (MLP=8).
__global__ void k_hist(const int* __restrict__ dst) {
    int i = blockIdx.x * blockDim.x + threadIdx.x;
    if (i < N_EDGES / 8) {
        int4 d0 = __ldcs((const int4*)dst + 2 * i);
        int4 d1 = __ldcs((const int4*)dst + 2 * i + 1);
        atomicAdd(&g_counts[d0.x], 1);
        atomicAdd(&g_counts[d0.y], 1);
        atomicAdd(&g_counts[d0.z], 1);
        atomicAdd(&g_counts[d0.w], 1);
        atomicAdd(&g_counts[d1.x], 1);
        atomicAdd(&g_counts[d1.y], 1);
        atomicAdd(&g_counts[d1.z], 1);
        atomicAdd(&g_counts[d1.w], 1);
    }
}

// Single-block one-pass scan: thread t owns 20 contiguous counts.
// warp-shfl scan of the 1024 per-thread sums, 2 barriers total.
__global__ __launch_bounds__(1024) void k_scan() {
    const int PER = 20;                       // 1024*20 = 20480 >= 20000
    int t = threadIdx.x;
    int lane = t & 31, w = t >> 5;
    int base = t * PER;

    int c[PER];
    int sum = 0;
    #pragma unroll
    for (int j = 0; j < PER; j++) {
        int idx = base + j;
        c[j] = (idx < N_NODES) ? g_counts[idx] : 0;
        sum += c[j];
    }

    // inclusive warp scan of sum
    int inc = sum;
    #pragma unroll
    for (int o = 1; o < 32; o <<= 1) {
        int nv = __shfl_up_sync(0xffffffffu, inc, o);
        if (lane >= o) inc += nv;
    }
    __shared__ int wsum[32];
    if (lane == 31) wsum[w] = inc;
    __syncthreads();
    if (w == 0) {
        int v = wsum[lane];
        #pragma unroll
        for (int o = 1; o < 32; o <<= 1) {
            int nv = __shfl_up_sync(0xffffffffu, v, o);
            if (lane >= o) v += nv;
        }
        wsum[lane] = v;
    }
    __syncthreads();

    int excl = ((w > 0) ? wsum[w - 1] : 0) + inc - sum;
    int running = excl;
    #pragma unroll
    for (int j = 0; j < PER; j++) {
        int idx = base + j;
        if (idx < N_NODES) {
            g_offsets[idx] = running;
            g_cursor[idx] = running;
        }
        running += c[j];
    }
    if (t == 1023) g_offsets[N_NODES] = running;
}

// 8 edges per thread; also re-zeroes g_counts for the next execution
// (counts were last read by k_scan, which precedes this kernel).
__global__ void k_place(const int* __restrict__ dst) {
    int i = blockIdx.x * blockDim.x + threadIdx.x;
    if (i < N_EDGES / 8) {
        int4 d0 = __ldcs((const int4*)dst + 2 * i);
        int4 d1 = __ldcs((const int4*)dst + 2 * i + 1);
        int e = i * 8;
        g_edge_idx[atomicAdd(&g_cursor[d0.x], 1)] = e;
        g_edge_idx[atomicAdd(&g_cursor[d0.y], 1)] = e + 1;
        g_edge_idx[atomicAdd(&g_cursor[d0.z], 1)] = e + 2;
        g_edge_idx[atomicAdd(&g_cursor[d0.w], 1)] = e + 3;
        g_edge_idx[atomicAdd(&g_cursor[d1.x], 1)] = e + 4;
        g_edge_idx[atomicAdd(&g_cursor[d1.y], 1)] = e + 5;
        g_edge_idx[atomicAdd(&g_cursor[d1.z], 1)] = e + 6;
        g_edge_idx[atomicAdd(&g_cursor[d1.w], 1)] = e + 7;
    }
    if (i < N_NODES) g_counts[i] = 0;
}

// One block (4 warps) per node.
// Per edge per warp:
//   - lane l loads float4 of key_feat (512B coalesced); head h = l/4;
//     16-dim dot via 2x shfl_xor within lane-groups of 4.
//   - lane l owns flat value elements [6l, 6l+6): since 6*(l%4)+5 < 24,
//     the whole range is in head l/4 = the lane's own head, so the lane's
//     own ex weights them — NO broadcast shfls. 3x LDG.64, fully coalesced
//     (768B per warp per edge).
//   - softmax max skipped (logits sigma~0.35, exp can't overflow; w is
//     shift-invariant); division deferred to epilogue.
// 2x edge unroll for MLP; __ldcs streaming hints (zero reuse).
__global__ __launch_bounds__(128) void k_main(
    const float* __restrict__ value,
    const float* __restrict__ key_feat,
    const float* __restrict__ q0,
    const float* __restrict__ q1,
    float* __restrict__ out0,
    float* __restrict__ out1,
    float* __restrict__ prelogits)
{
    int n = blockIdx.x;
    int t = threadIdx.x;
    int lane = t & 31;
    int warp = t >> 5;

    __shared__ float4 qs4[32];
    __shared__ float sacc[192];
    __shared__ float ssum[NHEAD];
    float* qs = (float*)qs4;

    // q[n] flat (8,16): channel c: [q0[c], q1[c,0..2]] at qs[4c..4c+3]
    if (t < 32) qs[t * 4] = q0[n * 32 + t];
    if (t >= 32) {
        int u = t - 32;                 // [0,96)
        qs[(u / 3) * 4 + 1 + (u % 3)] = q1[n * 96 + u];
    }
    sacc[t] = 0.f;
    if (t < 64) sacc[128 + t] = 0.f;
    if (t < NHEAD) ssum[t] = 0.f;
    __syncthreads();

    int off = g_offsets[n];
    int deg = g_offsets[n + 1] - off;

    float acc[6] = {0.f, 0.f, 0.f, 0.f, 0.f, 0.f};
    float s_reg = 0.f;
    const float scale = 0.08838834764831845f;  // 1/sqrt(128)
    bool leader = (lane & 3) == 0;
    int h = lane >> 2;

    float4 qv = qs4[lane];

    int idx = warp;
    for (; idx + 4 < deg; idx += 8) {
        int e0 = g_edge_idx[off + idx];
        int e1 = g_edge_idx[off + idx + 4];
        const float4* kp0 = (const float4*)key_feat + e0 * 32 + lane;
        const float4* kp1 = (const float4*)key_feat + e1 * 32 + lane;
        const float2* vp0 = (const float2*)(value + e0 * 192) + 3 * lane;
        const float2* vp1 = (const float2*)(value + e1 * 192) + 3 * lane;

        float4 k0 = __ldcs(kp0);
        float4 k1 = __ldcs(kp1);
        float2 a0 = __ldcs(vp0), a1 = __ldcs(vp0 + 1), a2 = __ldcs(vp0 + 2);
        float2 b0 = __ldcs(vp1), b1 = __ldcs(vp1 + 1), b2 = __ldcs(vp1 + 2);

        float p0 = k0.x * qv.x + k0.y * qv.y + k0.z * qv.z + k0.w * qv.w;
        float p1 = k1.x * qv.x + k1.y * qv.y + k1.z * qv.z + k1.w * qv.w;
        p0 += __shfl_xor_sync(0xffffffffu, p0, 1);
        p1 += __shfl_xor_sync(0xffffffffu, p1, 1);
        p0 += __shfl_xor_sync(0xffffffffu, p0, 2);
        p1 += __shfl_xor_sync(0xffffffffu, p1, 2);
        p0 *= scale;
        p1 *= scale;
        if (leader) {
            __stcs(&prelogits[e0 * 8 + h], p0);
            __stcs(&prelogits[e1 * 8 + h], p1);
        }
        float ex0 = __expf(p0);
        float ex1 = __expf(p1);
        if (leader) s_reg += ex0 + ex1;

        acc[0] += ex0 * a0.x; acc[1] += ex0 * a0.y;
        acc[2] += ex0 * a1.x; acc[3] += ex0 * a1.y;
        acc[4] += ex0 * a2.x; acc[5] += ex0 * a2.y;
        acc[0] += ex1 * b0.x; acc[1] += ex1 * b0.y;
        acc[2] += ex1 * b1.x; acc[3] += ex1 * b1.y;
        acc[4] += ex1 * b2.x; acc[5] += ex1 * b2.y;
    }
    if (idx < deg) {
        int e0 = g_edge_idx[off + idx];
        const float4* kp0 = (const float4*)key_feat + e0 * 32 + lane;
        const float2* vp0 = (const float2*)(value + e0 * 192) + 3 * lane;
        float4 k0 = __ldcs(kp0);
        float2 a0 = __ldcs(vp0), a1 = __ldcs(vp0 + 1), a2 = __ldcs(vp0 + 2);
        float p0 = k0.x * qv.x + k0.y * qv.y + k0.z * qv.z + k0.w * qv.w;
        p0 += __shfl_xor_sync(0xffffffffu, p0, 1);
        p0 += __shfl_xor_sync(0xffffffffu, p0, 2);
        p0 *= scale;
        if (leader) __stcs(&prelogits[e0 * 8 + h], p0);
        float ex0 = __expf(p0);
        if (leader) s_reg += ex0;
        acc[0] += ex0 * a0.x; acc[1] += ex0 * a0.y;
        acc[2] += ex0 * a1.x; acc[3] += ex0 * a1.y;
        acc[4] += ex0 * a2.x; acc[5] += ex0 * a2.y;
    }

    #pragma unroll
    for (int j = 0; j < 6; j++) atomicAdd(&sacc[6 * lane + j], acc[j]);
    if (leader) atomicAdd(&ssum[h], s_reg);
    __syncthreads();

    // feat flat j in (64,3): out0 = (c<32, d=0) -> j=3c, head c/8
    //                        out1 = (c>=32)     -> j=96+u, head 4+u/24
    if (t < 32) {
        float s = ssum[t >> 3];
        out0[n * 32 + t] = (s > 0.f) ? sacc[3 * t] / s : 0.f;
    } else {
        int u = t - 32;
        float s = ssum[4 + u / 24];
        out1[n * 96 + u] = (s > 0.f) ? sacc[96 + u] / s : 0.f;
    }
}

extern "C" void kernel_launch(void* const* d_in, const int* in_sizes, int n_in,
                              void* d_out, int out_size)
{
    const float* value    = (const float*)d_in[0];
    const float* key_feat = (const float*)d_in[1];
    const float* q0       = (const float*)d_in[2];
    const float* q1       = (const float*)d_in[3];
    const int*   dst      = (const int*)d_in[4];

    float* out       = (float*)d_out;
    float* out0      = out;                 // N*32*1
    float* out1      = out + 640000;        // N*32*3
    float* prelogits = out + 2560000;       // E*8

    k_hist<<<(N_EDGES / 8 + 255) / 256, 256>>>(dst);
    k_scan<<<1, 1024>>>();
    k_place<<<(N_EDGES / 8 + 255) / 256, 256>>>(dst);
    k_main<<<N_NODES, 128>>>(value, key_feat, q0, q1, out0, out1, prelogits);
}

// round 6
// speedup vs baseline: 1.5317x; 1.0192x over previous
#include <cuda_runtime.h>

#define N_NODES 20000
#define N_EDGES 640000
#define NHEAD 8

// CSR scratch (device globals — no allocation allowed)
// g_counts is zero at module load; k_scan re-zeroes it after reading so
// every run (correctness + each graph replay) starts from counts==0.
__device__ int g_counts[N_NODES];
__device__ int g_offsets[N_NODES + 1];
__device__ int g_rank[N_EDGES];
__device__ int g_edge_idx[N_EDGES];

// Single atomic pass: rank of each edge within its destination node.
// 8 edges/thread; ranks stored coalesced as int4.
__global__ void k_rank(const int* __restrict__ dst) {
    int i = blockIdx.x * blockDim.x + threadIdx.x;
    if (i < N_EDGES / 8) {
        int4 d0 = __ldcs((const int4*)dst + 2 * i);
        int4 d1 = __ldcs((const int4*)dst + 2 * i + 1);
        int4 r0, r1;
        r0.x = atomicAdd(&g_counts[d0.x], 1);
        r0.y = atomicAdd(&g_counts[d0.y], 1);
        r0.z = atomicAdd(&g_counts[d0.z], 1);
        r0.w = atomicAdd(&g_counts[d0.w], 1);
        r1.x = atomicAdd(&g_counts[d1.x], 1);
        r1.y = atomicAdd(&g_counts[d1.y], 1);
        r1.z = atomicAdd(&g_counts[d1.z], 1);
        r1.w = atomicAdd(&g_counts[d1.w], 1);
        ((int4*)g_rank)[2 * i] = r0;
        ((int4*)g_rank)[2 * i + 1] = r1;
    }
}

// Single-block one-pass scan: thread t owns 20 contiguous counts.
// warp-shfl scan of the 1024 per-thread sums, 2 barriers total.
// Also re-zeroes g_counts (last reader) for the next execution.
__global__ __launch_bounds__(1024) void k_scan() {
    const int PER = 20;                       // 1024*20 = 20480 >= 20000
    int t = threadIdx.x;
    int lane = t & 31, w = t >> 5;
    int base = t * PER;

    int c[PER];
    int sum = 0;
    #pragma unroll
    for (int j = 0; j < PER; j++) {
        int idx = base + j;
        c[j] = (idx < N_NODES) ? g_counts[idx] : 0;
        if (idx < N_NODES) g_counts[idx] = 0;
        sum += c[j];
    }

    // inclusive warp scan of sum
    int inc = sum;
    #pragma unroll
    for (int o = 1; o < 32; o <<= 1) {
        int nv = __shfl_up_sync(0xffffffffu, inc, o);
        if (lane >= o) inc += nv;
    }
    __shared__ int wsum[32];
    if (lane == 31) wsum[w] = inc;
    __syncthreads();
    if (w == 0) {
        int v = wsum[lane];
        #pragma unroll
        for (int o = 1; o < 32; o <<= 1) {
            int nv = __shfl_up_sync(0xffffffffu, v, o);
            if (lane >= o) v += nv;
        }
        wsum[lane] = v;
    }
    __syncthreads();

    int excl = ((w > 0) ? wsum[w - 1] : 0) + inc - sum;
    int running = excl;
    #pragma unroll
    for (int j = 0; j < PER; j++) {
        int idx = base + j;
        if (idx < N_NODES) g_offsets[idx] = running;
        running += c[j];
    }
    if (t == 1023) g_offsets[N_NODES] = running;
}

// Zero atomics: final position = offsets[dst[e]] + rank[e].
// offsets table is 80KB -> L1/L2 resident gather; stores scattered 4B.
__global__ void k_scatter(const int* __restrict__ dst) {
    int i = blockIdx.x * blockDim.x + threadIdx.x;
    if (i < N_EDGES / 8) {
        int4 d0 = __ldcs((const int4*)dst + 2 * i);
        int4 d1 = __ldcs((const int4*)dst + 2 * i + 1);
        int4 r0 = ((const int4*)g_rank)[2 * i];
        int4 r1 = ((const int4*)g_rank)[2 * i + 1];
        int e = i * 8;
        g_edge_idx[g_offsets[d0.x] + r0.x] = e;
        g_edge_idx[g_offsets[d0.y] + r0.y] = e + 1;
        g_edge_idx[g_offsets[d0.z] + r0.z] = e + 2;
        g_edge_idx[g_offsets[d0.w] + r0.w] = e + 3;
        g_edge_idx[g_offsets[d1.x] + r1.x] = e + 4;
        g_edge_idx[g_offsets[d1.y] + r1.y] = e + 5;
        g_edge_idx[g_offsets[d1.z] + r1.z] = e + 6;
        g_edge_idx[g_offsets[d1.w] + r1.w] = e + 7;
    }
}

// One block (4 warps) per node.
// Per edge per warp:
//   - lane l loads float4 of key_feat (512B coalesced); head h = l/4;
//     16-dim dot via 2x shfl_xor within lane-groups of 4.
//   - lane l owns flat value elements [6l, 6l+6): since 6*(l%4)+5 < 24,
//     the whole range is in head l/4 = the lane's own head, so the lane's
//     own ex weights them — NO broadcast shfls. 3x LDG.64, fully coalesced
//     (768B per warp per edge).
//   - softmax max skipped (logits sigma~0.35, exp can't overflow; w is
//     shift-invariant); division deferred to epilogue.
// 2x edge unroll for MLP; __ldcs streaming hints (zero reuse).
__global__ __launch_bounds__(128) void k_main(
    const float* __restrict__ value,
    const float* __restrict__ key_feat,
    const float* __restrict__ q0,
    const float* __restrict__ q1,
    float* __restrict__ out0,
    float* __restrict__ out1,
    float* __restrict__ prelogits)
{
    int n = blockIdx.x;
    int t = threadIdx.x;
    int lane = t & 31;
    int warp = t >> 5;

    __shared__ float4 qs4[32];
    __shared__ float sacc[192];
    __shared__ float ssum[NHEAD];
    float* qs = (float*)qs4;

    // q[n] flat (8,16): channel c: [q0[c], q1[c,0..2]] at qs[4c..4c+3]
    if (t < 32) qs[t * 4] = q0[n * 32 + t];
    if (t >= 32) {
        int u = t - 32;                 // [0,96)
        qs[(u / 3) * 4 + 1 + (u % 3)] = q1[n * 96 + u];
    }
    sacc[t] = 0.f;
    if (t < 64) sacc[128 + t] = 0.f;
    if (t < NHEAD) ssum[t] = 0.f;
    __syncthreads();

    int off = g_offsets[n];
    int deg = g_offsets[n + 1] - off;

    float acc[6] = {0.f, 0.f, 0.f, 0.f, 0.f, 0.f};
    float s_reg = 0.f;
    const float scale = 0.08838834764831845f;  // 1/sqrt(128)
    bool leader = (lane & 3) == 0;
    int h = lane >> 2;

    float4 qv = qs4[lane];

    int idx = warp;
    for (; idx + 4 < deg; idx += 8) {
        int e0 = g_edge_idx[off + idx];
        int e1 = g_edge_idx[off + idx + 4];
        const float4* kp0 = (const float4*)key_feat + e0 * 32 + lane;
        const float4* kp1 = (const float4*)key_feat + e1 * 32 + lane;
        const float2* vp0 = (const float2*)(value + e0 * 192) + 3 * lane;
        const float2* vp1 = (const float2*)(value + e1 * 192) + 3 * lane;

        float4 k0 = __ldcs(kp0);
        float4 k1 = __ldcs(kp1);
        float2 a0 = __ldcs(vp0), a1 = __ldcs(vp0 + 1), a2 = __ldcs(vp0 + 2);
        float2 b0 = __ldcs(vp1), b1 = __ldcs(vp1 + 1), b2 = __ldcs(vp1 + 2);

        float p0 = k0.x * qv.x + k0.y * qv.y + k0.z * qv.z + k0.w * qv.w;
        float p1 = k1.x * qv.x + k1.y * qv.y + k1.z * qv.z + k1.w * qv.w;
        p0 += __shfl_xor_sync(0xffffffffu, p0, 1);
        p1 += __shfl_xor_sync(0xffffffffu, p1, 1);
        p0 += __shfl_xor_sync(0xffffffffu, p0, 2);
        p1 += __shfl_xor_sync(0xffffffffu, p1, 2);
        p0 *= scale;
        p1 *= scale;
        if (leader) {
            __stcs(&prelogits[e0 * 8 + h], p0);
            __stcs(&prelogits[e1 * 8 + h], p1);
        }
        float ex0 = __expf(p0);
        float ex1 = __expf(p1);
        if (leader) s_reg += ex0 + ex1;

        acc[0] += ex0 * a0.x; acc[1] += ex0 * a0.y;
        acc[2] += ex0 * a1.x; acc[3] += ex0 * a1.y;
        acc[4] += ex0 * a2.x; acc[5] += ex0 * a2.y;
        acc[0] += ex1 * b0.x; acc[1] += ex1 * b0.y;
        acc[2] += ex1 * b1.x; acc[3] += ex1 * b1.y;
        acc[4] += ex1 * b2.x; acc[5] += ex1 * b2.y;
    }
    if (idx < deg) {
        int e0 = g_edge_idx[off + idx];
        const float4* kp0 = (const float4*)key_feat + e0 * 32 + lane;
        const float2* vp0 = (const float2*)(value + e0 * 192) + 3 * lane;
        float4 k0 = __ldcs(kp0);
        float2 a0 = __ldcs(vp0), a1 = __ldcs(vp0 + 1), a2 = __ldcs(vp0 + 2);
        float p0 = k0.x * qv.x + k0.y * qv.y + k0.z * qv.z + k0.w * qv.w;
        p0 += __shfl_xor_sync(0xffffffffu, p0, 1);
        p0 += __shfl_xor_sync(0xffffffffu, p0, 2);
        p0 *= scale;
        if (leader) __stcs(&prelogits[e0 * 8 + h], p0);
        float ex0 = __expf(p0);
        if (leader) s_reg += ex0;
        acc[0] += ex0 * a0.x; acc[1] += ex0 * a0.y;
        acc[2] += ex0 * a1.x; acc[3] += ex0 * a1.y;
        acc[4] += ex0 * a2.x; acc[5] += ex0 * a2.y;
    }

    #pragma unroll
    for (int j = 0; j < 6; j++) atomicAdd(&sacc[6 * lane + j], acc[j]);
    if (leader) atomicAdd(&ssum[h], s_reg);
    __syncthreads();

    // feat flat j in (64,3): out0 = (c<32, d=0) -> j=3c, head c/8
    //                        out1 = (c>=32)     -> j=96+u, head 4+u/24
    if (t < 32) {
        float s = ssum[t >> 3];
        out0[n * 32 + t] = (s > 0.f) ? sacc[3 * t] / s : 0.f;
    } else {
        int u = t - 32;
        float s = ssum[4 + u / 24];
        out1[n * 96 + u] = (s > 0.f) ? sacc[96 + u] / s : 0.f;
    }
}

extern "C" void kernel_launch(void* const* d_in, const int* in_sizes, int n_in,
                              void* d_out, int out_size)
{
    const float* value    = (const float*)d_in[0];
    const float* key_feat = (const float*)d_in[1];
    const float* q0       = (const float*)d_in[2];
    const float* q1       = (const float*)d_in[3];
    const int*   dst      = (const int*)d_in[4];

    float* out       = (float*)d_out;
    float* out0      = out;                 // N*32*1
    float* out1      = out + 640000;        // N*32*3
    float* prelogits = out + 2560000;       // E*8

    k_rank<<<(N_EDGES / 8 + 255) / 256, 256>>>(dst);
    k_scan<<<1, 1024>>>();
    k_scatter<<<(N_EDGES / 8 + 255) / 256, 256>>>(dst);
    k_main<<<N_NODES, 128>>>(value, key_feat, q0, q1, out0, out1, prelogits);
}

// round 11
// speedup vs baseline: 1.5352x; 1.0023x over previous
#include <cuda_runtime.h>

#define N_NODES 20000
#define N_EDGES 640000
#define NHEAD 8

// CSR scratch (device globals — no allocation allowed)
// g_counts/g_done are zero at module load; each is re-zeroed in-kernel after
// its last read so every run (correctness + graph replays) is deterministic.
__device__ int g_counts[N_NODES];
__device__ int g_offsets[N_NODES + 1];
__device__ int g_rank[N_EDGES];
__device__ int g_edge_idx[N_EDGES];
__device__ unsigned g_done;

// Fused rank + scan.
// Phase 1 (all 79 blocks, 1024 thr): one atomic pass computing each edge's
// rank within its destination node (8 edges/thread, ranks stored as int4).
// Phase 2 (last finishing block only, canonical threadfence+counter pattern):
// exclusive scan of counts -> offsets (warp-shfl, 2 barriers), re-zeroing
// counts as it reads them.
__global__ __launch_bounds__(1024) void k_rankscan(const int* __restrict__ dst) {
    int i = blockIdx.x * blockDim.x + threadIdx.x;
    if (i < N_EDGES / 8) {
        int4 d0 = __ldcs((const int4*)dst + 2 * i);
        int4 d1 = __ldcs((const int4*)dst + 2 * i + 1);
        int4 r0, r1;
        r0.x = atomicAdd(&g_counts[d0.x], 1);
        r0.y = atomicAdd(&g_counts[d0.y], 1);
        r0.z = atomicAdd(&g_counts[d0.z], 1);
        r0.w = atomicAdd(&g_counts[d0.w], 1);
        r1.x = atomicAdd(&g_counts[d1.x], 1);
        r1.y = atomicAdd(&g_counts[d1.y], 1);
        r1.z = atomicAdd(&g_counts[d1.z], 1);
        r1.w = atomicAdd(&g_counts[d1.w], 1);
        ((int4*)g_rank)[2 * i] = r0;
        ((int4*)g_rank)[2 * i + 1] = r1;
    }

    __threadfence();
    __syncthreads();
    __shared__ bool is_last;
    if (threadIdx.x == 0)
        is_last = (atomicAdd(&g_done, 1u) == gridDim.x - 1);
    __syncthreads();
    if (!is_last) return;
    if (threadIdx.x == 0) g_done = 0;   // reset for next execution

    // ---- inline scan (this block has 1024 threads) ----
    const int PER = 20;                 // 1024*20 = 20480 >= 20000
    int t = threadIdx.x;
    int lane = t & 31, w = t >> 5;
    int base = t * PER;

    int c[PER];
    int sum = 0;
    #pragma unroll
    for (int j = 0; j < PER; j++) {
        int idx = base + j;
        c[j] = (idx < N_NODES) ? g_counts[idx] : 0;
        if (idx < N_NODES) g_counts[idx] = 0;   // re-zero for next execution
        sum += c[j];
    }

    int inc = sum;
    #pragma unroll
    for (int o = 1; o < 32; o <<= 1) {
        int nv = __shfl_up_sync(0xffffffffu, inc, o);
        if (lane >= o) inc += nv;
    }
    __shared__ int wsum[32];
    if (lane == 31) wsum[w] = inc;
    __syncthreads();
    if (w == 0) {
        int v = wsum[lane];
        #pragma unroll
        for (int o = 1; o < 32; o <<= 1) {
            int nv = __shfl_up_sync(0xffffffffu, v, o);
            if (lane >= o) v += nv;
        }
        wsum[lane] = v;
    }
    __syncthreads();

    int excl = ((w > 0) ? wsum[w - 1] : 0) + inc - sum;
    int running = excl;
    #pragma unroll
    for (int j = 0; j < PER; j++) {
        int idx = base + j;
        if (idx < N_NODES) g_offsets[idx] = running;
        running += c[j];
    }
    if (t == 1023) g_offsets[N_NODES] = running;
}

// Zero atomics: final position = offsets[dst[e]] + rank[e].
// offsets table is 80KB -> L1/L2 resident gather; stores scattered 4B.
__global__ void k_scatter(const int* __restrict__ dst) {
    int i = blockIdx.x * blockDim.x + threadIdx.x;
    if (i < N_EDGES / 8) {
        int4 d0 = __ldcs((const int4*)dst + 2 * i);
        int4 d1 = __ldcs((const int4*)dst + 2 * i + 1);
        int4 r0 = ((const int4*)g_rank)[2 * i];
        int4 r1 = ((const int4*)g_rank)[2 * i + 1];
        int e = i * 8;
        g_edge_idx[g_offsets[d0.x] + r0.x] = e;
        g_edge_idx[g_offsets[d0.y] + r0.y] = e + 1;
        g_edge_idx[g_offsets[d0.z] + r0.z] = e + 2;
        g_edge_idx[g_offsets[d0.w] + r0.w] = e + 3;
        g_edge_idx[g_offsets[d1.x] + r1.x] = e + 4;
        g_edge_idx[g_offsets[d1.y] + r1.y] = e + 5;
        g_edge_idx[g_offsets[d1.z] + r1.z] = e + 6;
        g_edge_idx[g_offsets[d1.w] + r1.w] = e + 7;
    }
}

// One block (4 warps) per node.
// Per edge per warp:
//   - lane l loads float4 of key_feat (512B coalesced); head h = l/4;
//     16-dim dot via 2x shfl_xor within lane-groups of 4.
//   - lane l owns flat value elements [6l, 6l+6) — all inside head l/4,
//     whose ex the lane already holds: 3x LDG.64 coalesced, no broadcasts.
//   - softmax max skipped (logits sigma~0.35, exp can't overflow; w is
//     shift-invariant); division deferred to epilogue.
// 2x edge unroll; __ldcs/__stcs streaming (zero reuse).
// min-blocks 12 caps regs (~42) -> 75% occupancy for more outstanding loads.
__global__ __launch_bounds__(128, 12) void k_main(
    const float* __restrict__ value,
    const float* __restrict__ key_feat,
    const float* __restrict__ q0,
    const float* __restrict__ q1,
    float* __restrict__ out0,
    float* __restrict__ out1,
    float* __restrict__ prelogits)
{
    int n = blockIdx.x;
    int t = threadIdx.x;
    int lane = t & 31;
    int warp = t >> 5;

    __shared__ float4 qs4[32];
    __shared__ float sacc[192];
    __shared__ float ssum[NHEAD];
    float* qs = (float*)qs4;

    // q[n] flat (8,16): channel c: [q0[c], q1[c,0..2]] at qs[4c..4c+3]
    if (t < 32) qs[t * 4] = q0[n * 32 + t];
    if (t >= 32) {
        int u = t - 32;                 // [0,96)
        qs[(u / 3) * 4 + 1 + (u % 3)] = q1[n * 96 + u];
    }
    sacc[t] = 0.f;
    if (t < 64) sacc[128 + t] = 0.f;
    if (t < NHEAD) ssum[t] = 0.f;
    __syncthreads();

    int off = g_offsets[n];
    int deg = g_offsets[n + 1] - off;

    float acc[6] = {0.f, 0.f, 0.f, 0.f, 0.f, 0.f};
    float s_reg = 0.f;
    const float scale = 0.08838834764831845f;  // 1/sqrt(128)
    bool leader = (lane & 3) == 0;
    int h = lane >> 2;

    float4 qv = qs4[lane];

    int idx = warp;
    for (; idx + 4 < deg; idx += 8) {
        int e0 = g_edge_idx[off + idx];
        int e1 = g_edge_idx[off + idx + 4];
        const float4* kp0 = (const float4*)key_feat + e0 * 32 + lane;
        const float4* kp1 = (const float4*)key_feat + e1 * 32 + lane;
        const float2* vp0 = (const float2*)(value + e0 * 192) + 3 * lane;
        const float2* vp1 = (const float2*)(value + e1 * 192) + 3 * lane;

        float4 k0 = __ldcs(kp0);
        float4 k1 = __ldcs(kp1);
        float2 a0 = __ldcs(vp0), a1 = __ldcs(vp0 + 1), a2 = __ldcs(vp0 + 2);
        float2 b0 = __ldcs(vp1), b1 = __ldcs(vp1 + 1), b2 = __ldcs(vp1 + 2);

        float p0 = k0.x * qv.x + k0.y * qv.y + k0.z * qv.z + k0.w * qv.w;
        float p1 = k1.x * qv.x + k1.y * qv.y + k1.z * qv.z + k1.w * qv.w;
        p0 += __shfl_xor_sync(0xffffffffu, p0, 1);
        p1 += __shfl_xor_sync(0xffffffffu, p1, 1);
        p0 += __shfl_xor_sync(0xffffffffu, p0, 2);
        p1 += __shfl_xor_sync(0xffffffffu, p1, 2);
        p0 *= scale;
        p1 *= scale;
        if (leader) {
            __stcs(&prelogits[e0 * 8 + h], p0);
            __stcs(&prelogits[e1 * 8 + h], p1);
        }
        float ex0 = __expf(p0);
        float ex1 = __expf(p1);
        if (leader) s_reg += ex0 + ex1;

        acc[0] += ex0 * a0.x; acc[1] += ex0 * a0.y;
        acc[2] += ex0 * a1.x; acc[3] += ex0 * a1.y;
        acc[4] += ex0 * a2.x; acc[5] += ex0 * a2.y;
        acc[0] += ex1 * b0.x; acc[1] += ex1 * b0.y;
        acc[2] += ex1 * b1.x; acc[3] += ex1 * b1.y;
        acc[4] += ex1 * b2.x; acc[5] += ex1 * b2.y;
    }
    if (idx < deg) {
        int e0 = g_edge_idx[off + idx];
        const float4* kp0 = (const float4*)key_feat + e0 * 32 + lane;
        const float2* vp0 = (const float2*)(value + e0 * 192) + 3 * lane;
        float4 k0 = __ldcs(kp0);
        float2 a0 = __ldcs(vp0), a1 = __ldcs(vp0 + 1), a2 = __ldcs(vp0 + 2);
        float p0 = k0.x * qv.x + k0.y * qv.y + k0.z * qv.z + k0.w * qv.w;
        p0 += __shfl_xor_sync(0xffffffffu, p0, 1);
        p0 += __shfl_xor_sync(0xffffffffu, p0, 2);
        p0 *= scale;
        if (leader) __stcs(&prelogits[e0 * 8 + h], p0);
        float ex0 = __expf(p0);
        if (leader) s_reg += ex0;
        acc[0] += ex0 * a0.x; acc[1] += ex0 * a0.y;
        acc[2] += ex0 * a1.x; acc[3] += ex0 * a1.y;
        acc[4] += ex0 * a2.x; acc[5] += ex0 * a2.y;
    }

    #pragma unroll
    for (int j = 0; j < 6; j++) atomicAdd(&sacc[6 * lane + j], acc[j]);
    if (leader) atomicAdd(&ssum[h], s_reg);
    __syncthreads();

    // feat flat j in (64,3): out0 = (c<32, d=0) -> j=3c, head c/8
    //                        out1 = (c>=32)     -> j=96+u, head 4+u/24
    if (t < 32) {
        float s = ssum[t >> 3];
        out0[n * 32 + t] = (s > 0.f) ? sacc[3 * t] / s : 0.f;
    } else {
        int u = t - 32;
        float s = ssum[4 + u / 24];
        out1[n * 96 + u] = (s > 0.f) ? sacc[96 + u] / s : 0.f;
    }
}

extern "C" void kernel_launch(void* const* d_in, const int* in_sizes, int n_in,
                              void* d_out, int out_size)
{
    const float* value    = (const float*)d_in[0];
    const float* key_feat = (const float*)d_in[1];
    const float* q0       = (const float*)d_in[2];
    const float* q1       = (const float*)d_in[3];
    const int*   dst      = (const int*)d_in[4];

    float* out       = (float*)d_out;
    float* out0      = out;                 // N*32*1
    float* out1      = out + 640000;        // N*32*3
    float* prelogits = out + 2560000;       // E*8

    k_rankscan<<<(N_EDGES / 8 + 1023) / 1024, 1024>>>(dst);
    k_scatter<<<(N_EDGES / 8 + 255) / 256, 256>>>(dst);
    k_main<<<N_NODES, 128>>>(value, key_feat, q0, q1, out0, out1, prelogits);
}

// round 12
// speedup vs baseline: 1.5626x; 1.0179x over previous
#include <cuda_runtime.h>

#define N_NODES 20000
#define N_EDGES 640000
#define NHEAD 8

// CSR scratch (device globals — no allocation allowed)
// g_counts is zero at module load; k_scan re-zeroes it after reading so
// every run (correctness + each graph replay) starts from counts==0.
__device__ int g_counts[N_NODES];
__device__ int g_offsets[N_NODES + 1];
__device__ int g_rank[N_EDGES];
__device__ int g_edge_idx[N_EDGES];

// Single atomic pass: rank of each edge within its destination node.
// 8 edges/thread; ranks stored coalesced as int4. No fence — visibility is
// guaranteed by the kernel boundary.
__global__ void k_rank(const int* __restrict__ dst) {
    int i = blockIdx.x * blockDim.x + threadIdx.x;
    if (i < N_EDGES / 8) {
        int4 d0 = __ldcs((const int4*)dst + 2 * i);
        int4 d1 = __ldcs((const int4*)dst + 2 * i + 1);
        int4 r0, r1;
        r0.x = atomicAdd(&g_counts[d0.x], 1);
        r0.y = atomicAdd(&g_counts[d0.y], 1);
        r0.z = atomicAdd(&g_counts[d0.z], 1);
        r0.w = atomicAdd(&g_counts[d0.w], 1);
        r1.x = atomicAdd(&g_counts[d1.x], 1);
        r1.y = atomicAdd(&g_counts[d1.y], 1);
        r1.z = atomicAdd(&g_counts[d1.z], 1);
        r1.w = atomicAdd(&g_counts[d1.w], 1);
        ((int4*)g_rank)[2 * i] = r0;
        ((int4*)g_rank)[2 * i + 1] = r1;
    }
}

// Single-block one-pass scan: thread t owns 20 contiguous counts.
// warp-shfl scan of the 1024 per-thread sums, 2 barriers total.
// Also re-zeroes g_counts (last reader) for the next execution.
__global__ __launch_bounds__(1024) void k_scan() {
    const int PER = 20;                       // 1024*20 = 20480 >= 20000
    int t = threadIdx.x;
    int lane = t & 31, w = t >> 5;
    int base = t * PER;

    int c[PER];
    int sum = 0;
    #pragma unroll
    for (int j = 0; j < PER; j++) {
        int idx = base + j;
        c[j] = (idx < N_NODES) ? g_counts[idx] : 0;
        if (idx < N_NODES) g_counts[idx] = 0;
        sum += c[j];
    }

    int inc = sum;
    #pragma unroll
    for (int o = 1; o < 32; o <<= 1) {
        int nv = __shfl_up_sync(0xffffffffu, inc, o);
        if (lane >= o) inc += nv;
    }
    __shared__ int wsum[32];
    if (lane == 31) wsum[w] = inc;
    __syncthreads();
    if (w == 0) {
        int v = wsum[lane];
        #pragma unroll
        for (int o = 1; o < 32; o <<= 1) {
            int nv = __shfl_up_sync(0xffffffffu, v, o);
            if (lane >= o) v += nv;
        }
        wsum[lane] = v;
    }
    __syncthreads();

    int excl = ((w > 0) ? wsum[w - 1] : 0) + inc - sum;
    int running = excl;
    #pragma unroll
    for (int j = 0; j < PER; j++) {
        int idx = base + j;
        if (idx < N_NODES) g_offsets[idx] = running;
        running += c[j];
    }
    if (t == 1023) g_offsets[N_NODES] = running;
}

// Zero atomics: final position = offsets[dst[e]] + rank[e].
// offsets table is 80KB -> L1/L2 resident gather; stores scattered 4B.
__global__ void k_scatter(const int* __restrict__ dst) {
    int i = blockIdx.x * blockDim.x + threadIdx.x;
    if (i < N_EDGES / 8) {
        int4 d0 = __ldcs((const int4*)dst + 2 * i);
        int4 d1 = __ldcs((const int4*)dst + 2 * i + 1);
        int4 r0 = ((const int4*)g_rank)[2 * i];
        int4 r1 = ((const int4*)g_rank)[2 * i + 1];
        int e = i * 8;
        g_edge_idx[g_offsets[d0.x] + r0.x] = e;
        g_edge_idx[g_offsets[d0.y] + r0.y] = e + 1;
        g_edge_idx[g_offsets[d0.z] + r0.z] = e + 2;
        g_edge_idx[g_offsets[d0.w] + r0.w] = e + 3;
        g_edge_idx[g_offsets[d1.x] + r1.x] = e + 4;
        g_edge_idx[g_offsets[d1.y] + r1.y] = e + 5;
        g_edge_idx[g_offsets[d1.z] + r1.z] = e + 6;
        g_edge_idx[g_offsets[d1.w] + r1.w] = e + 7;
    }
}

// One block (4 warps) per node.
// Per edge per warp:
//   - lane l loads float4 of key_feat (512B coalesced); head h = l/4;
//     16-dim dot via 2x shfl_xor within lane-groups of 4.
//   - lane l owns flat value elements [6l, 6l+6) — all inside head l/4,
//     whose ex the lane already holds: 3x LDG.64 coalesced, no broadcasts.
//   - softmax max skipped (logits sigma~0.35, exp can't overflow; w is
//     shift-invariant); division deferred to epilogue.
// 2x edge unroll; __ldcs/__stcs streaming (zero reuse).
// min-blocks 12 caps regs (~42) -> 75% occupancy (measured ~ -11us).
__global__ __launch_bounds__(128, 12) void k_main(
    const float* __restrict__ value,
    const float* __restrict__ key_feat,
    const float* __restrict__ q0,
    const float* __restrict__ q1,
    float* __restrict__ out0,
    float* __restrict__ out1,
    float* __restrict__ prelogits)
{
    int n = blockIdx.x;
    int t = threadIdx.x;
    int lane = t & 31;
    int warp = t >> 5;

    __shared__ float4 qs4[32];
    __shared__ float sacc[192];
    __shared__ float ssum[NHEAD];
    float* qs = (float*)qs4;

    // q[n] flat (8,16): channel c: [q0[c], q1[c,0..2]] at qs[4c..4c+3]
    if (t < 32) qs[t * 4] = q0[n * 32 + t];
    if (t >= 32) {
        int u = t - 32;                 // [0,96)
        qs[(u / 3) * 4 + 1 + (u % 3)] = q1[n * 96 + u];
    }
    sacc[t] = 0.f;
    if (t < 64) sacc[128 + t] = 0.f;
    if (t < NHEAD) ssum[t] = 0.f;
    __syncthreads();

    int off = g_offsets[n];
    int deg = g_offsets[n + 1] - off;

    float acc[6] = {0.f, 0.f, 0.f, 0.f, 0.f, 0.f};
    float s_reg = 0.f;
    const float scale = 0.08838834764831845f;  // 1/sqrt(128)
    bool leader = (lane & 3) == 0;
    int h = lane >> 2;

    float4 qv = qs4[lane];

    int idx = warp;
    for (; idx + 4 < deg; idx += 8) {
        int e0 = g_edge_idx[off + idx];
        int e1 = g_edge_idx[off + idx + 4];
        const float4* kp0 = (const float4*)key_feat + e0 * 32 + lane;
        const float4* kp1 = (const float4*)key_feat + e1 * 32 + lane;
        const float2* vp0 = (const float2*)(value + e0 * 192) + 3 * lane;
        const float2* vp1 = (const float2*)(value + e1 * 192) + 3 * lane;

        float4 k0 = __ldcs(kp0);
        float4 k1 = __ldcs(kp1);
        float2 a0 = __ldcs(vp0), a1 = __ldcs(vp0 + 1), a2 = __ldcs(vp0 + 2);
        float2 b0 = __ldcs(vp1), b1 = __ldcs(vp1 + 1), b2 = __ldcs(vp1 + 2);

        float p0 = k0.x * qv.x + k0.y * qv.y + k0.z * qv.z + k0.w * qv.w;
        float p1 = k1.x * qv.x + k1.y * qv.y + k1.z * qv.z + k1.w * qv.w;
        p0 += __shfl_xor_sync(0xffffffffu, p0, 1);
        p1 += __shfl_xor_sync(0xffffffffu, p1, 1);
        p0 += __shfl_xor_sync(0xffffffffu, p0, 2);
        p1 += __shfl_xor_sync(0xffffffffu, p1, 2);
        p0 *= scale;
        p1 *= scale;
        if (leader) {
            __stcs(&prelogits[e0 * 8 + h], p0);
            __stcs(&prelogits[e1 * 8 + h], p1);
        }
        float ex0 = __expf(p0);
        float ex1 = __expf(p1);
        if (leader) s_reg += ex0 + ex1;

        acc[0] += ex0 * a0.x; acc[1] += ex0 * a0.y;
        acc[2] += ex0 * a1.x; acc[3] += ex0 * a1.y;
        acc[4] += ex0 * a2.x; acc[5] += ex0 * a2.y;
        acc[0] += ex1 * b0.x; acc[1] += ex1 * b0.y;
        acc[2] += ex1 * b1.x; acc[3] += ex1 * b1.y;
        acc[4] += ex1 * b2.x; acc[5] += ex1 * b2.y;
    }
    if (idx < deg) {
        int e0 = g_edge_idx[off + idx];
        const float4* kp0 = (const float4*)key_feat + e0 * 32 + lane;
        const float2* vp0 = (const float2*)(value + e0 * 192) + 3 * lane;
        float4 k0 = __ldcs(kp0);
        float2 a0 = __ldcs(vp0), a1 = __ldcs(vp0 + 1), a2 = __ldcs(vp0 + 2);
        float p0 = k0.x * qv.x + k0.y * qv.y + k0.z * qv.z + k0.w * qv.w;
        p0 += __shfl_xor_sync(0xffffffffu, p0, 1);
        p0 += __shfl_xor_sync(0xffffffffu, p0, 2);
        p0 *= scale;
        if (leader) __stcs(&prelogits[e0 * 8 + h], p0);
        float ex0 = __expf(p0);
        if (leader) s_reg += ex0;
        acc[0] += ex0 * a0.x; acc[1] += ex0 * a0.y;
        acc[2] += ex0 * a1.x; acc[3] += ex0 * a1.y;
        acc[4] += ex0 * a2.x; acc[5] += ex0 * a2.y;
    }

    #pragma unroll
    for (int j = 0; j < 6; j++) atomicAdd(&sacc[6 * lane + j], acc[j]);
    if (leader) atomicAdd(&ssum[h], s_reg);
    __syncthreads();

    // feat flat j in (64,3): out0 = (c<32, d=0) -> j=3c, head c/8
    //                        out1 = (c>=32)     -> j=96+u, head 4+u/24
    if (t < 32) {
        float s = ssum[t >> 3];
        out0[n * 32 + t] = (s > 0.f) ? sacc[3 * t] / s : 0.f;
    } else {
        int u = t - 32;
        float s = ssum[4 + u / 24];
        out1[n * 96 + u] = (s > 0.f) ? sacc[96 + u] / s : 0.f;
    }
}

extern "C" void kernel_launch(void* const* d_in, const int* in_sizes, int n_in,
                              void* d_out, int out_size)
{
    const float* value    = (const float*)d_in[0];
    const float* key_feat = (const float*)d_in[1];
    const float* q0       = (const float*)d_in[2];
    const float* q1       = (const float*)d_in[3];
    const int*   dst      = (const int*)d_in[4];

    float* out       = (float*)d_out;
    float* out0      = out;                 // N*32*1
    float* out1      = out + 640000;        // N*32*3
    float* prelogits = out + 2560000;       // E*8

    k_rank<<<(N_EDGES / 8 + 255) / 256, 256>>>(dst);
    k_scan<<<1, 1024>>>();
    k_scatter<<<(N_EDGES / 8 + 255) / 256, 256>>>(dst);
    k_main<<<N_NODES, 128>>>(value, key_feat, q0, q1, out0, out1, prelogits);
}